// round 1
// baseline (speedup 1.0000x reference)
#include <cuda_runtime.h>

typedef unsigned long long ull;

#define NN    4096
#define KKC   3
#define BB    8
#define TT    12
#define BT    96          // B*T
#define FOUT  12
#define HIDD  64
#define RTOT  (KKC*NN)    // 12288 rows (k,n flattened)
#define ROWS  128         // CTA row tile
#define MC    32          // K chunk
#define SPLITK 16
#define KPER  (NN/SPLITK) // 256
#define NCH   (KPER/MC)   // 8
#define APAD  36          // 128 rows x 36 floats  (36*4B stride, 16B aligned)
#define XPAD  100         // 32 m x 100 floats

static_assert(RTOT % ROWS == 0, "");

constexpr int SBUF_FLOATS = ROWS*APAD + MC*XPAD;   // 7808 floats per buffer
constexpr int SMEM_BYTES  = 2 * SBUF_FLOATS * 4;   // 62464 B (double buffered)

// Split-K accumulator scratch: C[r][bt], fp32
__device__ float g_C[RTOT * BT];

__device__ __forceinline__ ull f2dup(float f){
    ull r; asm("mov.b64 %0, {%1, %1};" : "=l"(r) : "f"(f)); return r;
}
__device__ __forceinline__ void ffma2(ull &d, ull a, ull b){
    asm("fma.rn.f32x2 %0, %1, %2, %3;" : "=l"(d) : "l"(a), "l"(b), "l"(d));
}

// ---------------------------------------------------------------------------
__global__ void zero_C(){
    int i = blockIdx.x * blockDim.x + threadIdx.x;
    if (i < RTOT*BT) g_C[i] = 0.f;
}

// ---------------------------------------------------------------------------
// GEMM: C[r][c] += sum_m adj[r][m] * x[c][m]
//   adj viewed as [12288][4096] (k,n flattened), x viewed as [96][4096] (b,t flattened)
// CTA: 128 rows x 96 cols, K range = 256 m (8 chunks of 32), atomicAdd combine.
#define LDG_CHUNK(ch) do { \
    int m0 = mbase + (ch)*MC; \
    _Pragma("unroll") \
    for (int p=0;p<4;p++){ int idx=p*256+tid; int rr=idx>>3, mg=idx&7; \
        pa[p] = *reinterpret_cast<const float4*>(&adj[(size_t)(r0+rr)*NN + m0 + mg*4]); } \
    _Pragma("unroll") \
    for (int p=0;p<3;p++){ int idx=p*256+tid; int cc=idx>>3, mg=idx&7; \
        px[p] = *reinterpret_cast<const float4*>(&x[(size_t)cc*NN + m0 + mg*4]); } \
} while(0)

#define STS_CHUNK(buf) do { \
    float* As_ = smem + (buf)*SBUF_FLOATS; \
    float* Xs_ = As_ + ROWS*APAD; \
    _Pragma("unroll") \
    for (int p=0;p<4;p++){ int idx=p*256+tid; int rr=idx>>3, mg=idx&7; \
        *reinterpret_cast<float4*>(&As_[rr*APAD + mg*4]) = pa[p]; } \
    _Pragma("unroll") \
    for (int p=0;p<3;p++){ int idx=p*256+tid; int cc=idx>>3, mg=idx&7; \
        Xs_[(mg*4+0)*XPAD + cc] = px[p].x; \
        Xs_[(mg*4+1)*XPAD + cc] = px[p].y; \
        Xs_[(mg*4+2)*XPAD + cc] = px[p].z; \
        Xs_[(mg*4+3)*XPAD + cc] = px[p].w; } \
} while(0)

__global__ __launch_bounds__(256,1) void gemm_kernel(
        const float* __restrict__ adj, const float* __restrict__ x)
{
    extern __shared__ float smem[];
    const int tid = threadIdx.x;
    const int tc  = tid & 7;     // 8 thread-cols  -> 12 output cols each
    const int tr  = tid >> 3;    // 32 thread-rows -> 4  output rows each
    const int r0    = blockIdx.x * ROWS;
    const int mbase = blockIdx.y * KPER;

    float4 pa[4], px[3];

    ull acc[4][6];
    #pragma unroll
    for (int i=0;i<4;i++)
        #pragma unroll
        for (int j=0;j<6;j++) acc[i][j] = 0ull;

    LDG_CHUNK(0);
    STS_CHUNK(0);
    __syncthreads();

    int pbuf = 0;
    for (int ch=0; ch<NCH; ch++){
        if (ch+1 < NCH) LDG_CHUNK(ch+1);

        const float* As = smem + pbuf*SBUF_FLOATS;
        const float* Xs = As + ROWS*APAD;

        #pragma unroll
        for (int mb=0; mb<MC; mb+=4){
            float4 a4[4];
            #pragma unroll
            for (int i=0;i<4;i++)
                a4[i] = *reinterpret_cast<const float4*>(&As[(tr*4+i)*APAD + mb]);
            #pragma unroll
            for (int q=0;q<4;q++){
                const float* xb = &Xs[(mb+q)*XPAD + tc*12];
                ulonglong2 bA = *reinterpret_cast<const ulonglong2*>(xb);
                ulonglong2 bB = *reinterpret_cast<const ulonglong2*>(xb+4);
                ulonglong2 bC = *reinterpret_cast<const ulonglong2*>(xb+8);
                ull Bv[6] = {bA.x, bA.y, bB.x, bB.y, bC.x, bC.y};
                #pragma unroll
                for (int i=0;i<4;i++){
                    float av = (q==0) ? a4[i].x : (q==1) ? a4[i].y : (q==2) ? a4[i].z : a4[i].w;
                    ull ad = f2dup(av);
                    #pragma unroll
                    for (int j=0;j<6;j++) ffma2(acc[i][j], ad, Bv[j]);
                }
            }
        }

        if (ch+1 < NCH) STS_CHUNK(1-pbuf);
        __syncthreads();
        pbuf ^= 1;
    }

    #pragma unroll
    for (int i=0;i<4;i++){
        int rr = r0 + tr*4 + i;
        #pragma unroll
        for (int j=0;j<6;j++){
            union { ull u; float f[2]; } v; v.u = acc[i][j];
            int cc = tc*12 + j*2;
            atomicAdd(&g_C[rr*BT + cc    ], v.f[0]);
            atomicAdd(&g_C[rr*BT + cc + 1], v.f[1]);
        }
    }
}

// ---------------------------------------------------------------------------
// Epilogue: per (b,n) thread.
//   y[t][k]    = C[(k*4096+n)*96 + b*12 + t]
//   cheb[t][j] = relu(sum_k y[t][k]*cheb_w[j][k])
//   sgc[o]     = sum_{t,j} cheb[t][j]*gcn_w[o][t][j] + gcn_b[o]
//   a/g        = dilated conv over n (only kw=1 contributes since W=1)
//   out        = a*sigmoid(g) + sgc
__global__ __launch_bounds__(256) void epilogue_kernel(
    const float* __restrict__ x,
    const float* __restrict__ cheb_w,
    const float* __restrict__ gcn_w,
    const float* __restrict__ gcn_b,
    const float* __restrict__ glu1_w,
    const float* __restrict__ glu1_b,
    const float* __restrict__ glu2_w,
    const float* __restrict__ glu2_b,
    float* __restrict__ out)
{
    __shared__ __align__(16) float gws[TT*HIDD*FOUT];  // [t][j][o]  9216 floats
    __shared__ float cws[HIDD*3];                      // [j][k]
    __shared__ float w1s[FOUT*6*3], w2s[FOUT*6*3];     // [o][c][kh]
    __shared__ float gbs[FOUT], b1s[FOUT], b2s[FOUT];

    const int tid = threadIdx.x;
    for (int i=tid; i<TT*HIDD*FOUT; i+=256){
        int o = i % FOUT; int tj = i / FOUT; int t = tj >> 6; int j = tj & 63;
        gws[i] = gcn_w[(o*TT + t)*HIDD + j];
    }
    for (int i=tid; i<HIDD*3; i+=256) cws[i] = cheb_w[i];
    for (int i=tid; i<FOUT*18; i+=256){
        int kh = i % 3; int oc = i / 3;
        w1s[i] = glu1_w[(oc*3 + kh)*3 + 1];   // kw = 1 only
        w2s[i] = glu2_w[(oc*3 + kh)*3 + 1];
    }
    if (tid < FOUT){ gbs[tid]=gcn_b[tid]; b1s[tid]=glu1_b[tid]; b2s[tid]=glu2_b[tid]; }
    __syncthreads();

    const int bn = blockIdx.x*256 + tid;
    const int b  = bn >> 12;
    const int n  = bn & (NN-1);

    float y[TT][3];
    #pragma unroll
    for (int k=0;k<3;k++)
        #pragma unroll
        for (int t=0;t<TT;t++)
            y[t][k] = g_C[((size_t)((k<<12) + n))*BT + b*TT + t];

    ull acc[6];
    #pragma unroll
    for (int j=0;j<6;j++) acc[j] = 0ull;

    #pragma unroll
    for (int t=0;t<TT;t++){
        #pragma unroll 8
        for (int j=0;j<HIDD;j++){
            float c = y[t][0]*cws[j*3] + y[t][1]*cws[j*3+1] + y[t][2]*cws[j*3+2];
            c = fmaxf(c, 0.f);
            ull cd = f2dup(c);
            const float* gp = &gws[(t*HIDD + j)*FOUT];
            ulonglong2 g0 = *reinterpret_cast<const ulonglong2*>(gp);
            ulonglong2 g1 = *reinterpret_cast<const ulonglong2*>(gp+4);
            ulonglong2 g2 = *reinterpret_cast<const ulonglong2*>(gp+8);
            ffma2(acc[0], cd, g0.x); ffma2(acc[1], cd, g0.y);
            ffma2(acc[2], cd, g1.x); ffma2(acc[3], cd, g1.y);
            ffma2(acc[4], cd, g2.x); ffma2(acc[5], cd, g2.y);
        }
    }

    // Dilated GLU inputs: positions n-2, n, n+2, channels 0..5 (a) and 6..11 (g)
    float xu[6][3], xv[6][3];
    #pragma unroll
    for (int c=0;c<6;c++){
        #pragma unroll
        for (int kh=0;kh<3;kh++){
            int pos = n + 2*kh - 2;
            bool ok = (pos >= 0) && (pos < NN);
            xu[c][kh] = ok ? x[((size_t)b*TT + c    )*NN + pos] : 0.f;
            xv[c][kh] = ok ? x[((size_t)b*TT + 6 + c)*NN + pos] : 0.f;
        }
    }

    #pragma unroll
    for (int o=0;o<FOUT;o++){
        float av = b1s[o], gv = b2s[o];
        #pragma unroll
        for (int c=0;c<6;c++)
            #pragma unroll
            for (int kh=0;kh<3;kh++){
                av += w1s[(o*6+c)*3+kh]*xu[c][kh];
                gv += w2s[(o*6+c)*3+kh]*xv[c][kh];
            }
        float sg = 1.f/(1.f + __expf(-gv));
        union { ull u; float f[2]; } vv; vv.u = acc[o>>1];
        float sgc = vv.f[o&1] + gbs[o];
        out[((size_t)b*FOUT + o)*NN + n] = av*sg + sgc;
    }
}

// ---------------------------------------------------------------------------
extern "C" void kernel_launch(void* const* d_in, const int* in_sizes, int n_in,
                              void* d_out, int out_size)
{
    (void)in_sizes; (void)n_in; (void)out_size;
    const float* x      = (const float*)d_in[0];
    const float* adj    = (const float*)d_in[1];
    const float* cheb_w = (const float*)d_in[2];
    const float* gcn_w  = (const float*)d_in[3];
    const float* gcn_b  = (const float*)d_in[4];
    const float* glu1_w = (const float*)d_in[5];
    const float* glu1_b = (const float*)d_in[6];
    const float* glu2_w = (const float*)d_in[7];
    const float* glu2_b = (const float*)d_in[8];
    float* out = (float*)d_out;

    zero_C<<<(RTOT*BT + 255)/256, 256>>>();

    cudaFuncSetAttribute(gemm_kernel,
                         cudaFuncAttributeMaxDynamicSharedMemorySize, SMEM_BYTES);
    gemm_kernel<<<dim3(RTOT/ROWS, SPLITK), 256, SMEM_BYTES>>>(adj, x);

    epilogue_kernel<<<(BB*NN)/256, 256>>>(x, cheb_w, gcn_w, gcn_b,
                                          glu1_w, glu1_b, glu2_w, glu2_b, out);
}

// round 2
// speedup vs baseline: 1.6455x; 1.6455x over previous
#include <cuda_runtime.h>

typedef unsigned long long ull;

#define NN    4096
#define KKC   3
#define BB    8
#define TT    12
#define BT    96          // B*T
#define FOUT  12
#define HIDD  64
#define RTOT  (KKC*NN)    // 12288 rows (k,n flattened)
#define ROWS  128         // CTA row tile
#define MC    32          // K chunk
#define SPLITK 16
#define KPER  (NN/SPLITK) // 256
#define NCH   (KPER/MC)   // 8
#define APAD  36
#define XPAD  100

static_assert(RTOT % ROWS == 0, "");

constexpr int SBUF_FLOATS = ROWS*APAD + MC*XPAD;   // 7808 floats per buffer
constexpr int SMEM_BYTES  = 2 * SBUF_FLOATS * 4;   // 62464 B (double buffered)
constexpr int CN = RTOT * BT;                      // 1,179,648

// Split-K partials (written with plain stores, every cell exactly once) + reduced C
__device__ float g_part[SPLITK * CN];              // 75.5 MB
__device__ float g_C[CN];                          // 4.7 MB

__device__ __forceinline__ ull f2dup(float f){
    ull r; asm("mov.b64 %0, {%1, %1};" : "=l"(r) : "f"(f)); return r;
}
__device__ __forceinline__ void ffma2(ull &d, ull a, ull b){
    asm("fma.rn.f32x2 %0, %1, %2, %3;" : "=l"(d) : "l"(a), "l"(b), "l"(d));
}

// ---------------------------------------------------------------------------
// GEMM: part[s][r][c] = sum_{m in s-th K slice} adj[r][m] * x[c][m]
#define LDG_CHUNK(ch) do { \
    int m0 = mbase + (ch)*MC; \
    _Pragma("unroll") \
    for (int p=0;p<4;p++){ int idx=p*256+tid; int rr=idx>>3, mg=idx&7; \
        pa[p] = *reinterpret_cast<const float4*>(&adj[(size_t)(r0+rr)*NN + m0 + mg*4]); } \
    _Pragma("unroll") \
    for (int p=0;p<3;p++){ int idx=p*256+tid; int cc=idx>>3, mg=idx&7; \
        px[p] = *reinterpret_cast<const float4*>(&x[(size_t)cc*NN + m0 + mg*4]); } \
} while(0)

#define STS_CHUNK(buf) do { \
    float* As_ = smem + (buf)*SBUF_FLOATS; \
    float* Xs_ = As_ + ROWS*APAD; \
    _Pragma("unroll") \
    for (int p=0;p<4;p++){ int idx=p*256+tid; int rr=idx>>3, mg=idx&7; \
        *reinterpret_cast<float4*>(&As_[rr*APAD + mg*4]) = pa[p]; } \
    _Pragma("unroll") \
    for (int p=0;p<3;p++){ int idx=p*256+tid; int cc=idx>>3, mg=idx&7; \
        Xs_[(mg*4+0)*XPAD + cc] = px[p].x; \
        Xs_[(mg*4+1)*XPAD + cc] = px[p].y; \
        Xs_[(mg*4+2)*XPAD + cc] = px[p].z; \
        Xs_[(mg*4+3)*XPAD + cc] = px[p].w; } \
} while(0)

__global__ __launch_bounds__(256,1) void gemm_kernel(
        const float* __restrict__ adj, const float* __restrict__ x)
{
    extern __shared__ float smem[];
    const int tid = threadIdx.x;
    const int tc  = tid & 7;     // 8 thread-cols  -> 12 output cols each
    const int tr  = tid >> 3;    // 32 thread-rows -> 4  output rows each
    const int r0    = blockIdx.x * ROWS;
    const int split = blockIdx.y;
    const int mbase = split * KPER;

    float4 pa[4], px[3];

    ull acc[4][6];
    #pragma unroll
    for (int i=0;i<4;i++)
        #pragma unroll
        for (int j=0;j<6;j++) acc[i][j] = 0ull;

    LDG_CHUNK(0);
    STS_CHUNK(0);
    __syncthreads();

    int pbuf = 0;
    for (int ch=0; ch<NCH; ch++){
        if (ch+1 < NCH) LDG_CHUNK(ch+1);

        const float* As = smem + pbuf*SBUF_FLOATS;
        const float* Xs = As + ROWS*APAD;

        #pragma unroll
        for (int mb=0; mb<MC; mb+=4){
            float4 a4[4];
            #pragma unroll
            for (int i=0;i<4;i++)
                a4[i] = *reinterpret_cast<const float4*>(&As[(tr*4+i)*APAD + mb]);
            #pragma unroll
            for (int q=0;q<4;q++){
                const float* xb = &Xs[(mb+q)*XPAD + tc*12];
                ulonglong2 bA = *reinterpret_cast<const ulonglong2*>(xb);
                ulonglong2 bB = *reinterpret_cast<const ulonglong2*>(xb+4);
                ulonglong2 bC = *reinterpret_cast<const ulonglong2*>(xb+8);
                ull Bv[6] = {bA.x, bA.y, bB.x, bB.y, bC.x, bC.y};
                #pragma unroll
                for (int i=0;i<4;i++){
                    float av = (q==0) ? a4[i].x : (q==1) ? a4[i].y : (q==2) ? a4[i].z : a4[i].w;
                    ull ad = f2dup(av);
                    #pragma unroll
                    for (int j=0;j<6;j++) ffma2(acc[i][j], ad, Bv[j]);
                }
            }
        }

        if (ch+1 < NCH) STS_CHUNK(1-pbuf);
        __syncthreads();
        pbuf ^= 1;
    }

    // Plain stores into this split's partial plane (no atomics, no pre-zero).
    float* pp = &g_part[(size_t)split * CN];
    #pragma unroll
    for (int i=0;i<4;i++){
        int rr = r0 + tr*4 + i;
        #pragma unroll
        for (int j=0;j<6;j++){
            int cc = tc*12 + j*2;
            *reinterpret_cast<ull*>(&pp[(size_t)rr*BT + cc]) = acc[i][j];
        }
    }
}

// ---------------------------------------------------------------------------
// Coalesced split-K reduction: g_C[i] = sum_s g_part[s][i]   (float4 per thread)
__global__ __launch_bounds__(256) void reduce_C(){
    int i = blockIdx.x*256 + threadIdx.x;            // float4 index, CN/4 total
    const float4* gp = reinterpret_cast<const float4*>(g_part);
    float4 s = gp[i];
    #pragma unroll
    for (int p=1;p<SPLITK;p++){
        float4 v = gp[(size_t)p*(CN/4) + i];
        s.x += v.x; s.y += v.y; s.z += v.z; s.w += v.w;
    }
    reinterpret_cast<float4*>(g_C)[i] = s;
}

// ---------------------------------------------------------------------------
__global__ __launch_bounds__(256) void epilogue_kernel(
    const float* __restrict__ x,
    const float* __restrict__ cheb_w,
    const float* __restrict__ gcn_w,
    const float* __restrict__ gcn_b,
    const float* __restrict__ glu1_w,
    const float* __restrict__ glu1_b,
    const float* __restrict__ glu2_w,
    const float* __restrict__ glu2_b,
    float* __restrict__ out)
{
    __shared__ __align__(16) float gws[TT*HIDD*FOUT];  // [t][j][o]
    __shared__ float cws[HIDD*3];                      // [j][k]
    __shared__ float w1s[FOUT*6*3], w2s[FOUT*6*3];     // [o][c][kh]
    __shared__ float gbs[FOUT], b1s[FOUT], b2s[FOUT];

    const int tid = threadIdx.x;
    for (int i=tid; i<TT*HIDD*FOUT; i+=256){
        int o = i % FOUT; int tj = i / FOUT; int t = tj >> 6; int j = tj & 63;
        gws[i] = gcn_w[(o*TT + t)*HIDD + j];
    }
    for (int i=tid; i<HIDD*3; i+=256) cws[i] = cheb_w[i];
    for (int i=tid; i<FOUT*18; i+=256){
        int kh = i % 3; int oc = i / 3;
        w1s[i] = glu1_w[(oc*3 + kh)*3 + 1];   // kw = 1 only (W dim is singleton)
        w2s[i] = glu2_w[(oc*3 + kh)*3 + 1];
    }
    if (tid < FOUT){ gbs[tid]=gcn_b[tid]; b1s[tid]=glu1_b[tid]; b2s[tid]=glu2_b[tid]; }
    __syncthreads();

    const int bn = blockIdx.x*256 + tid;
    const int b  = bn >> 12;
    const int n  = bn & (NN-1);

    float y[TT][3];
    #pragma unroll
    for (int k=0;k<3;k++)
        #pragma unroll
        for (int t=0;t<TT;t++)
            y[t][k] = g_C[((size_t)((k<<12) + n))*BT + b*TT + t];

    ull acc[6];
    #pragma unroll
    for (int j=0;j<6;j++) acc[j] = 0ull;

    #pragma unroll
    for (int t=0;t<TT;t++){
        #pragma unroll 8
        for (int j=0;j<HIDD;j++){
            float c = y[t][0]*cws[j*3] + y[t][1]*cws[j*3+1] + y[t][2]*cws[j*3+2];
            c = fmaxf(c, 0.f);
            ull cd = f2dup(c);
            const float* gp = &gws[(t*HIDD + j)*FOUT];
            ulonglong2 g0 = *reinterpret_cast<const ulonglong2*>(gp);
            ulonglong2 g1 = *reinterpret_cast<const ulonglong2*>(gp+4);
            ulonglong2 g2 = *reinterpret_cast<const ulonglong2*>(gp+8);
            ffma2(acc[0], cd, g0.x); ffma2(acc[1], cd, g0.y);
            ffma2(acc[2], cd, g1.x); ffma2(acc[3], cd, g1.y);
            ffma2(acc[4], cd, g2.x); ffma2(acc[5], cd, g2.y);
        }
    }

    // Dilated GLU: positions n-2, n, n+2; channels 0..5 (a) / 6..11 (g)
    float xu[6][3], xv[6][3];
    #pragma unroll
    for (int c=0;c<6;c++){
        #pragma unroll
        for (int kh=0;kh<3;kh++){
            int pos = n + 2*kh - 2;
            bool ok = (pos >= 0) && (pos < NN);
            xu[c][kh] = ok ? x[((size_t)b*TT + c    )*NN + pos] : 0.f;
            xv[c][kh] = ok ? x[((size_t)b*TT + 6 + c)*NN + pos] : 0.f;
        }
    }

    #pragma unroll
    for (int o=0;o<FOUT;o++){
        float av = b1s[o], gv = b2s[o];
        #pragma unroll
        for (int c=0;c<6;c++)
            #pragma unroll
            for (int kh=0;kh<3;kh++){
                av += w1s[(o*6+c)*3+kh]*xu[c][kh];
                gv += w2s[(o*6+c)*3+kh]*xv[c][kh];
            }
        float sg = 1.f/(1.f + __expf(-gv));
        union { ull u; float f[2]; } vv; vv.u = acc[o>>1];
        float sgc = vv.f[o&1] + gbs[o];
        out[((size_t)b*FOUT + o)*NN + n] = av*sg + sgc;
    }
}

// ---------------------------------------------------------------------------
extern "C" void kernel_launch(void* const* d_in, const int* in_sizes, int n_in,
                              void* d_out, int out_size)
{
    (void)in_sizes; (void)n_in; (void)out_size;
    const float* x      = (const float*)d_in[0];
    const float* adj    = (const float*)d_in[1];
    const float* cheb_w = (const float*)d_in[2];
    const float* gcn_w  = (const float*)d_in[3];
    const float* gcn_b  = (const float*)d_in[4];
    const float* glu1_w = (const float*)d_in[5];
    const float* glu1_b = (const float*)d_in[6];
    const float* glu2_w = (const float*)d_in[7];
    const float* glu2_b = (const float*)d_in[8];
    float* out = (float*)d_out;

    cudaFuncSetAttribute(gemm_kernel,
                         cudaFuncAttributeMaxDynamicSharedMemorySize, SMEM_BYTES);
    gemm_kernel<<<dim3(RTOT/ROWS, SPLITK), 256, SMEM_BYTES>>>(adj, x);

    reduce_C<<<(CN/4)/256, 256>>>();

    epilogue_kernel<<<(BB*NN)/256, 256>>>(x, cheb_w, gcn_w, gcn_b,
                                          glu1_w, glu1_b, glu2_w, glu2_b, out);
}

// round 4
// speedup vs baseline: 2.9894x; 1.8167x over previous
#include <cuda_runtime.h>
#include <cstdint>

typedef unsigned long long ull;
typedef unsigned int u32;

#define NN    4096
#define BB    8
#define TT    12
#define BT    96
#define FOUT  12
#define HIDD  64
#define ROWS  128          // M tile
#define COLS  96           // N tile (= BT)
#define KC    32           // K chunk
#define SPLITK 8
#define KPER  (NN/SPLITK)  // 512
#define NITS  (KPER/KC)    // 16
#define RTILES (3*NN/ROWS) // 96

#define CN (3*BB*TT*NN)    // 1,179,648

// stage layout in u32 units (pitch 20 u32 per row -> conflict-free LDS)
#define U_AH 0
#define U_AL (128*20)            // 2560
#define U_BH (2*128*20)          // 5120
#define U_BL (2*128*20 + 96*20)  // 7040
#define ST_U32 (2*128*20 + 2*96*20)   // 8960
#define ST_BYTES (ST_U32*4)           // 35840
#define SMEM_TOTAL (2*ST_BYTES)       // 71680

__device__ float g_part[SPLITK * CN];          // 37.7 MB partial planes
__device__ __align__(16) u32 g_xhi[BT*NN/2];   // x hi bf16 pairs
__device__ __align__(16) u32 g_xlo[BT*NN/2];   // x lo bf16 pairs

// ---------------------------------------------------------------- helpers
__device__ __forceinline__ u32 smem_u32(const void* p){
    u32 a; asm("{ .reg .u64 t; cvta.to.shared.u64 t, %1; cvt.u32.u64 %0, t; }"
               : "=r"(a) : "l"(p));
    return a;
}
__device__ __forceinline__ void cpasync16(u32 dst, const void* src){
    asm volatile("cp.async.cg.shared.global [%0], [%1], 16;"
                 :: "r"(dst), "l"(src) : "memory");
}
__device__ __forceinline__ void cp_commit(){
    asm volatile("cp.async.commit_group;" ::: "memory");
}
__device__ __forceinline__ void cp_wait0(){
    asm volatile("cp.async.wait_group 0;" ::: "memory");
}
// split f into bf16 hi (truncated) + bf16 lo (rn of remainder); pack pairs
__device__ __forceinline__ void cvt_pair(float f0, float f1, u32 &hi, u32 &lo){
    u32 u0 = __float_as_uint(f0), u1 = __float_as_uint(f1);
    hi = __byte_perm(u0, u1, 0x7632);
    float h0 = __uint_as_float(u0 & 0xFFFF0000u);
    float h1 = __uint_as_float(u1 & 0xFFFF0000u);
    float l0 = f0 - h0, l1 = f1 - h1;
    asm("cvt.rn.bf16x2.f32 %0, %1, %2;" : "=r"(lo) : "f"(l1), "f"(l0));
}
__device__ __forceinline__ void mma16816(float* c, const u32* a, const u32* b){
    asm volatile(
      "mma.sync.aligned.m16n8k16.row.col.f32.bf16.bf16.f32 "
      "{%0,%1,%2,%3}, {%4,%5,%6,%7}, {%8,%9}, {%0,%1,%2,%3};"
      : "+f"(c[0]), "+f"(c[1]), "+f"(c[2]), "+f"(c[3])
      : "r"(a[0]), "r"(a[1]), "r"(a[2]), "r"(a[3]), "r"(b[0]), "r"(b[1]));
}
__device__ __forceinline__ ull f2dup(float f){
    ull r; asm("mov.b64 %0, {%1, %1};" : "=l"(r) : "f"(f)); return r;
}
__device__ __forceinline__ void ffma2(ull &d, ull a, ull b){
    asm("fma.rn.f32x2 %0, %1, %2, %3;" : "=l"(d) : "l"(a), "l"(b), "l"(d));
}

// ---------------------------------------------------------------- split x
__global__ __launch_bounds__(256) void split_x(const float* __restrict__ x){
    int i = blockIdx.x*256 + threadIdx.x;        // pair index
    float2 f = reinterpret_cast<const float2*>(x)[i];
    u32 hi, lo;
    cvt_pair(f.x, f.y, hi, lo);
    g_xhi[i] = hi; g_xlo[i] = lo;
}

// ---------------------------------------------------------------- GEMM
// part[split][k][b][t][n] = sum_{m in split} adj[k*4096+n][m] * x[b*12+t][m]
__global__ __launch_bounds__(256, 2) void gemm_mma(const float* __restrict__ adj)
{
    extern __shared__ __align__(16) char smem[];
    u32* SU = reinterpret_cast<u32*>(smem);
    const u32 sb = smem_u32(smem);

    const int tid = threadIdx.x;
    const int wid = tid >> 5;
    const int lane = tid & 31;
    const int g   = lane >> 2;       // groupID
    const int tig = lane & 3;        // thread-in-group
    const int wm  = wid >> 1;        // warp row 0..3 (32 rows each)
    const int wn  = wid & 1;         // warp col 0..1 (48 cols each)

    const int r0    = blockIdx.x * ROWS;
    const int split = blockIdx.y;
    const int k0    = split * KPER;

    // A LDG mapping: row = tid>>1, half = tid&1 covers floats half*16..+15
    const int arow = tid >> 1;
    const int ahalf = tid & 1;
    const float4* aprow = reinterpret_cast<const float4*>(
        &adj[(size_t)(r0 + arow)*NN + k0 + ahalf*16]);

    float4 a4[2][4];

#define LOADA(set, it) do { \
    const float4* ap_ = aprow + (it)*8; \
    _Pragma("unroll") for (int p=0;p<4;p++) a4[set][p] = ap_[p]; } while(0)

    // B cp.async: 768 uint4 per iter (2 splits x 96 n x 4 groups)
#define CPB(stage, it) do { \
    u32 bbase_ = sb + (stage)*ST_BYTES; \
    int ku_ = (k0 + (it)*KC) >> 1; \
    _Pragma("unroll") for (int q=0;q<3;q++){ \
        int idx_ = q*256 + tid; \
        int sp_ = idx_ / 384, rem_ = idx_ - sp_*384; \
        int n_ = rem_ >> 2, j4_ = rem_ & 3; \
        const u32* src_ = (sp_ ? g_xlo : g_xhi) + (size_t)n_*2048 + ku_ + j4_*4; \
        u32 dst_ = bbase_ + ((sp_ ? U_BL : U_BH) + n_*20 + j4_*4)*4; \
        cpasync16(dst_, src_); } } while(0)

    // A convert + STS: 16 floats -> 8 hi u32 + 8 lo u32
#define STSA(stage, set) do { \
    u32* st_ = SU + (stage)*ST_U32; \
    uint4 hv0_, lv0_, hv1_, lv1_; \
    cvt_pair(a4[set][0].x, a4[set][0].y, hv0_.x, lv0_.x); \
    cvt_pair(a4[set][0].z, a4[set][0].w, hv0_.y, lv0_.y); \
    cvt_pair(a4[set][1].x, a4[set][1].y, hv0_.z, lv0_.z); \
    cvt_pair(a4[set][1].z, a4[set][1].w, hv0_.w, lv0_.w); \
    cvt_pair(a4[set][2].x, a4[set][2].y, hv1_.x, lv1_.x); \
    cvt_pair(a4[set][2].z, a4[set][2].w, hv1_.y, lv1_.y); \
    cvt_pair(a4[set][3].x, a4[set][3].y, hv1_.z, lv1_.z); \
    cvt_pair(a4[set][3].z, a4[set][3].w, hv1_.w, lv1_.w); \
    int o_ = arow*20 + ahalf*8; \
    *reinterpret_cast<uint4*>(st_ + U_AH + o_    ) = hv0_; \
    *reinterpret_cast<uint4*>(st_ + U_AH + o_ + 4) = hv1_; \
    *reinterpret_cast<uint4*>(st_ + U_AL + o_    ) = lv0_; \
    *reinterpret_cast<uint4*>(st_ + U_AL + o_ + 4) = lv1_; } while(0)

    float acc[2][6][4];
    #pragma unroll
    for (int mt=0;mt<2;mt++)
        #pragma unroll
        for (int nt=0;nt<6;nt++)
            #pragma unroll
            for (int c=0;c<4;c++) acc[mt][nt][c] = 0.f;

    // prologue
    LOADA(0, 0);
    CPB(0, 0); cp_commit();
    LOADA(1, 1);
    STSA(0, 0);
    cp_wait0();
    __syncthreads();

    for (int it = 0; it < NITS; it++){
        const int s = it & 1;
        if (it + 1 < NITS){
            CPB(s^1, it+1); cp_commit();
            STSA(s^1, (it+1)&1);
        }
        if (it + 2 < NITS) LOADA(s, it+2);

        const u32* ST = SU + s*ST_U32;
        #pragma unroll
        for (int kst = 0; kst < 2; kst++){
            const int jb = kst*8 + tig;
            u32 ah[2][4], al[2][4];
            #pragma unroll
            for (int mt=0;mt<2;mt++){
                int row = wm*32 + mt*16 + g;
                ah[mt][0] = ST[U_AH + row*20 + jb];
                ah[mt][1] = ST[U_AH + (row+8)*20 + jb];
                ah[mt][2] = ST[U_AH + row*20 + jb + 4];
                ah[mt][3] = ST[U_AH + (row+8)*20 + jb + 4];
                al[mt][0] = ST[U_AL + row*20 + jb];
                al[mt][1] = ST[U_AL + (row+8)*20 + jb];
                al[mt][2] = ST[U_AL + row*20 + jb + 4];
                al[mt][3] = ST[U_AL + (row+8)*20 + jb + 4];
            }
            u32 bh[6][2], bl[6][2];
            #pragma unroll
            for (int nt=0;nt<6;nt++){
                int n = wn*48 + nt*8 + g;
                bh[nt][0] = ST[U_BH + n*20 + jb];
                bh[nt][1] = ST[U_BH + n*20 + jb + 4];
                bl[nt][0] = ST[U_BL + n*20 + jb];
                bl[nt][1] = ST[U_BL + n*20 + jb + 4];
            }
            #pragma unroll
            for (int mt=0;mt<2;mt++)
                #pragma unroll
                for (int nt=0;nt<6;nt++){
                    mma16816(acc[mt][nt], ah[mt], bh[nt]);
                    mma16816(acc[mt][nt], ah[mt], bl[nt]);
                    mma16816(acc[mt][nt], al[mt], bh[nt]);
                }
        }

        if (it + 1 < NITS) cp_wait0();
        __syncthreads();
    }

    // store accumulators to this split's plane, layout [k][b][t][n]
    float* plane = g_part + (size_t)split * CN;
    #pragma unroll
    for (int mt=0;mt<2;mt++){
        #pragma unroll
        for (int nt=0;nt<6;nt++){
            int cbase = wn*48 + nt*8 + tig*2;
            #pragma unroll
            for (int h=0;h<2;h++){
                int r = r0 + wm*32 + mt*16 + g + h*8;
                int k = r >> 12, n = r & (NN-1);
                #pragma unroll
                for (int cc=0;cc<2;cc++){
                    int col = cbase + cc;
                    int b = col / TT, t = col - b*TT;
                    plane[(((size_t)(k*BB + b)*TT + t) << 12) + n] = acc[mt][nt][h*2+cc];
                }
            }
        }
    }
}

// ---------------------------------------------------------------- epilogue
__global__ __launch_bounds__(256) void epilogue_kernel(
    const float* __restrict__ x,
    const float* __restrict__ cheb_w,
    const float* __restrict__ gcn_w,
    const float* __restrict__ gcn_b,
    const float* __restrict__ glu1_w,
    const float* __restrict__ glu1_b,
    const float* __restrict__ glu2_w,
    const float* __restrict__ glu2_b,
    float* __restrict__ out)
{
    __shared__ __align__(16) float gws[TT*HIDD*FOUT];  // [t][j][o]
    __shared__ float cws[HIDD*3];
    __shared__ float w1s[FOUT*6*3], w2s[FOUT*6*3];
    __shared__ float gbs[FOUT], b1s[FOUT], b2s[FOUT];

    const int tid = threadIdx.x;
    for (int i=tid; i<TT*HIDD*FOUT; i+=256){
        int o = i % FOUT; int tj = i / FOUT; int t = tj >> 6; int j = tj & 63;
        gws[i] = gcn_w[(o*TT + t)*HIDD + j];
    }
    for (int i=tid; i<HIDD*3; i+=256) cws[i] = cheb_w[i];
    for (int i=tid; i<FOUT*18; i+=256){
        int kh = i % 3; int oc = i / 3;
        w1s[i] = glu1_w[(oc*3 + kh)*3 + 1];   // only kw=1 contributes (W==1)
        w2s[i] = glu2_w[(oc*3 + kh)*3 + 1];
    }
    if (tid < FOUT){ gbs[tid]=gcn_b[tid]; b1s[tid]=glu1_b[tid]; b2s[tid]=glu2_b[tid]; }
    __syncthreads();

    const int bn = blockIdx.x*256 + tid;
    const int b  = bn >> 12;
    const int n  = bn & (NN-1);

    // y[t][k] = sum over split planes (coalesced loads)
    float y[TT][3];
    #pragma unroll
    for (int k=0;k<3;k++)
        #pragma unroll
        for (int t=0;t<TT;t++){
            size_t off = (((size_t)(k*BB + b)*TT + t) << 12) + n;
            float s = 0.f;
            #pragma unroll
            for (int p=0;p<SPLITK;p++) s += g_part[(size_t)p*CN + off];
            y[t][k] = s;
        }

    ull acc[6];
    #pragma unroll
    for (int j=0;j<6;j++) acc[j] = 0ull;

    #pragma unroll
    for (int t=0;t<TT;t++){
        #pragma unroll 8
        for (int j=0;j<HIDD;j++){
            float c = y[t][0]*cws[j*3] + y[t][1]*cws[j*3+1] + y[t][2]*cws[j*3+2];
            c = fmaxf(c, 0.f);
            ull cd = f2dup(c);
            const float* gp = &gws[(t*HIDD + j)*FOUT];
            ulonglong2 g0 = *reinterpret_cast<const ulonglong2*>(gp);
            ulonglong2 g1 = *reinterpret_cast<const ulonglong2*>(gp+4);
            ulonglong2 g2 = *reinterpret_cast<const ulonglong2*>(gp+8);
            ffma2(acc[0], cd, g0.x); ffma2(acc[1], cd, g0.y);
            ffma2(acc[2], cd, g1.x); ffma2(acc[3], cd, g1.y);
            ffma2(acc[4], cd, g2.x); ffma2(acc[5], cd, g2.y);
        }
    }

    float xu[6][3], xv[6][3];
    #pragma unroll
    for (int c=0;c<6;c++){
        #pragma unroll
        for (int kh=0;kh<3;kh++){
            int pos = n + 2*kh - 2;
            bool ok = (pos >= 0) && (pos < NN);
            xu[c][kh] = ok ? x[((size_t)b*TT + c    )*NN + pos] : 0.f;
            xv[c][kh] = ok ? x[((size_t)b*TT + 6 + c)*NN + pos] : 0.f;
        }
    }

    #pragma unroll
    for (int o=0;o<FOUT;o++){
        float av = b1s[o], gv = b2s[o];
        #pragma unroll
        for (int c=0;c<6;c++)
            #pragma unroll
            for (int kh=0;kh<3;kh++){
                av += w1s[(o*6+c)*3+kh]*xu[c][kh];
                gv += w2s[(o*6+c)*3+kh]*xv[c][kh];
            }
        float sg = 1.f/(1.f + __expf(-gv));
        union { ull u; float f[2]; } vv; vv.u = acc[o>>1];
        float sgc = vv.f[o&1] + gbs[o];
        out[((size_t)b*FOUT + o)*NN + n] = av*sg + sgc;
    }
}

// ----------------------------------------------------------------
extern "C" void kernel_launch(void* const* d_in, const int* in_sizes, int n_in,
                              void* d_out, int out_size)
{
    (void)in_sizes; (void)n_in; (void)out_size;
    const float* x      = (const float*)d_in[0];
    const float* adj    = (const float*)d_in[1];
    const float* cheb_w = (const float*)d_in[2];
    const float* gcn_w  = (const float*)d_in[3];
    const float* gcn_b  = (const float*)d_in[4];
    const float* glu1_w = (const float*)d_in[5];
    const float* glu1_b = (const float*)d_in[6];
    const float* glu2_w = (const float*)d_in[7];
    const float* glu2_b = (const float*)d_in[8];
    float* out = (float*)d_out;

    split_x<<<(BT*NN/2)/256, 256>>>(x);

    cudaFuncSetAttribute(gemm_mma,
                         cudaFuncAttributeMaxDynamicSharedMemorySize, SMEM_TOTAL);
    gemm_mma<<<dim3(RTILES, SPLITK), 256, SMEM_TOTAL>>>(adj);

    epilogue_kernel<<<(BB*NN)/256, 256>>>(x, cheb_w, gcn_w, gcn_b,
                                          glu1_w, glu1_b, glu2_w, glu2_b, out);
}

// round 6
// speedup vs baseline: 3.0308x; 1.0139x over previous
#include <cuda_runtime.h>
#include <cstdint>

typedef unsigned long long ull;
typedef unsigned int u32;

#define NN    4096
#define BB    8
#define TT    12
#define BT    96
#define FOUT  12
#define HIDD  64
#define ROWS  128          // M tile
#define KC    32           // K chunk
#define SPLITK 8
#define KPER  (NN/SPLITK)  // 512
#define NITS  (KPER/KC)    // 16
#define RTILES (3*NN/ROWS) // 96

#define CN (3*BB*TT*NN)    // 1,179,648

// stage layout in u32 units (pitch 20 u32 per row -> conflict-free LDS/LDSM)
#define U_AH 0
#define U_AL (128*20)            // 2560
#define U_BH (2*128*20)          // 5120
#define U_BL (2*128*20 + 96*20)  // 7040
#define ST_U32 (2*128*20 + 2*96*20)   // 8960
#define ST_BYTES (ST_U32*4)           // 35840
#define SMEM_TOTAL (2*ST_BYTES)       // 71680

__device__ float g_part[SPLITK * CN];          // 37.7 MB partial planes
__device__ __align__(16) u32 g_xhi[BT*NN/2];   // x hi bf16 pairs
__device__ __align__(16) u32 g_xlo[BT*NN/2];   // x lo bf16 pairs

// ---------------------------------------------------------------- helpers
__device__ __forceinline__ u32 smem_u32(const void* p){
    u32 a; asm("{ .reg .u64 t; cvta.to.shared.u64 t, %1; cvt.u32.u64 %0, t; }"
               : "=r"(a) : "l"(p));
    return a;
}
__device__ __forceinline__ void cpasync16(u32 dst, const void* src){
    asm volatile("cp.async.cg.shared.global [%0], [%1], 16;"
                 :: "r"(dst), "l"(src) : "memory");
}
__device__ __forceinline__ void cp_commit(){
    asm volatile("cp.async.commit_group;" ::: "memory");
}
__device__ __forceinline__ void cp_wait0(){
    asm volatile("cp.async.wait_group 0;" ::: "memory");
}
__device__ __forceinline__ void ldsm4(u32* r, u32 addr){
    asm volatile("ldmatrix.sync.aligned.m8n8.x4.shared.b16 {%0,%1,%2,%3}, [%4];"
                 : "=r"(r[0]), "=r"(r[1]), "=r"(r[2]), "=r"(r[3]) : "r"(addr));
}
// split f into bf16 hi (truncated) + bf16 lo (rn of remainder); pack pairs
__device__ __forceinline__ void cvt_pair(float f0, float f1, u32 &hi, u32 &lo){
    u32 u0 = __float_as_uint(f0), u1 = __float_as_uint(f1);
    hi = __byte_perm(u0, u1, 0x7632);
    float h0 = __uint_as_float(u0 & 0xFFFF0000u);
    float h1 = __uint_as_float(u1 & 0xFFFF0000u);
    float l0 = f0 - h0, l1 = f1 - h1;
    asm("cvt.rn.bf16x2.f32 %0, %1, %2;" : "=r"(lo) : "f"(l1), "f"(l0));
}
__device__ __forceinline__ void mma16816(float* c, const u32* a, const u32* b){
    asm volatile(
      "mma.sync.aligned.m16n8k16.row.col.f32.bf16.bf16.f32 "
      "{%0,%1,%2,%3}, {%4,%5,%6,%7}, {%8,%9}, {%0,%1,%2,%3};"
      : "+f"(c[0]), "+f"(c[1]), "+f"(c[2]), "+f"(c[3])
      : "r"(a[0]), "r"(a[1]), "r"(a[2]), "r"(a[3]), "r"(b[0]), "r"(b[1]));
}
__device__ __forceinline__ ull f2dup(float f){
    ull r; asm("mov.b64 %0, {%1, %1};" : "=l"(r) : "f"(f)); return r;
}
__device__ __forceinline__ void ffma2(ull &d, ull a, ull b){
    asm("fma.rn.f32x2 %0, %1, %2, %3;" : "=l"(d) : "l"(a), "l"(b), "l"(d));
}

// ---------------------------------------------------------------- split x
__global__ __launch_bounds__(256) void split_x(const float* __restrict__ x){
    int i = blockIdx.x*256 + threadIdx.x;        // pair index
    float2 f = reinterpret_cast<const float2*>(x)[i];
    u32 hi, lo;
    cvt_pair(f.x, f.y, hi, lo);
    g_xhi[i] = hi; g_xlo[i] = lo;
}

// ---------------------------------------------------------------- GEMM
// part[split][k][b][t][n] = sum_{m in split} adj[k*4096+n][m] * x[b*12+t][m]
__global__ __launch_bounds__(256, 2) void gemm_mma(const float* __restrict__ adj)
{
    extern __shared__ __align__(16) char smem[];
    u32* SU = reinterpret_cast<u32*>(smem);
    const u32 sb = smem_u32(smem);

    const int tid = threadIdx.x;
    const int wid = tid >> 5;
    const int lane = tid & 31;
    const int tig = lane & 3;        // thread-in-group
    const int g   = lane >> 2;       // groupID
    const int wm  = wid >> 1;        // warp row 0..3 (32 rows each)
    const int wn  = wid & 1;         // warp col 0..1 (48 cols each)

    // ldmatrix addressing: lanes 0-15 give rows 0-15 (k-half 0 tiles),
    // lanes 16-31 give rows 0-15 again but at the second 16B k-half.
    const int lrow = lane & 15;
    const int lk16 = (lane >> 4) * 4;   // 0 or 4 u32

    const int r0    = blockIdx.x * ROWS;
    const int split = blockIdx.y;
    const int k0    = split * KPER;

    // A LDG mapping: row = tid>>1, half = tid&1 covers floats half*16..+15
    const int arow = tid >> 1;
    const int ahalf = tid & 1;
    const float4* aprow = reinterpret_cast<const float4*>(
        &adj[(size_t)(r0 + arow)*NN + k0 + ahalf*16]);

    float4 a4[2][4];

#define LOADA(set, it) do { \
    const float4* ap_ = aprow + (it)*8; \
    _Pragma("unroll") for (int p=0;p<4;p++) a4[set][p] = ap_[p]; } while(0)

#define CPB(stage, it) do { \
    u32 bbase_ = sb + (stage)*ST_BYTES; \
    int ku_ = (k0 + (it)*KC) >> 1; \
    _Pragma("unroll") for (int q=0;q<3;q++){ \
        int idx_ = q*256 + tid; \
        int sp_ = idx_ / 384, rem_ = idx_ - sp_*384; \
        int n_ = rem_ >> 2, j4_ = rem_ & 3; \
        const u32* src_ = (sp_ ? g_xlo : g_xhi) + (size_t)n_*2048 + ku_ + j4_*4; \
        u32 dst_ = bbase_ + ((sp_ ? U_BL : U_BH) + n_*20 + j4_*4)*4; \
        cpasync16(dst_, src_); } } while(0)

#define STSA(stage, set) do { \
    u32* st_ = SU + (stage)*ST_U32; \
    uint4 hv0_, lv0_, hv1_, lv1_; \
    cvt_pair(a4[set][0].x, a4[set][0].y, hv0_.x, lv0_.x); \
    cvt_pair(a4[set][0].z, a4[set][0].w, hv0_.y, lv0_.y); \
    cvt_pair(a4[set][1].x, a4[set][1].y, hv0_.z, lv0_.z); \
    cvt_pair(a4[set][1].z, a4[set][1].w, hv0_.w, lv0_.w); \
    cvt_pair(a4[set][2].x, a4[set][2].y, hv1_.x, lv1_.x); \
    cvt_pair(a4[set][2].z, a4[set][2].w, hv1_.y, lv1_.y); \
    cvt_pair(a4[set][3].x, a4[set][3].y, hv1_.z, lv1_.z); \
    cvt_pair(a4[set][3].z, a4[set][3].w, hv1_.w, lv1_.w); \
    int o_ = arow*20 + ahalf*8; \
    *reinterpret_cast<uint4*>(st_ + U_AH + o_    ) = hv0_; \
    *reinterpret_cast<uint4*>(st_ + U_AH + o_ + 4) = hv1_; \
    *reinterpret_cast<uint4*>(st_ + U_AL + o_    ) = lv0_; \
    *reinterpret_cast<uint4*>(st_ + U_AL + o_ + 4) = lv1_; } while(0)

    float acc[2][6][4];
    #pragma unroll
    for (int mt=0;mt<2;mt++)
        #pragma unroll
        for (int nt=0;nt<6;nt++)
            #pragma unroll
            for (int c=0;c<4;c++) acc[mt][nt][c] = 0.f;

    // prologue
    LOADA(0, 0);
    CPB(0, 0); cp_commit();
    LOADA(1, 1);
    STSA(0, 0);
    cp_wait0();
    __syncthreads();

    for (int it = 0; it < NITS; it++){
        const int s = it & 1;
        if (it + 1 < NITS){
            CPB(s^1, it+1); cp_commit();
            STSA(s^1, (it+1)&1);
        }
        if (it + 2 < NITS) LOADA(s, it+2);

        const u32 stb = sb + s*ST_BYTES;
        #pragma unroll
        for (int kst = 0; kst < 2; kst++){
            const u32 koff = (u32)(kst*8 + lk16);
            // A fragments via ldmatrix.x4:
            // r0=(m0-7,k0-7)=a0, r1=(m8-15,k0-7)=a1, r2=(m0-7,k8-15)=a2, r3=a3
            u32 ah[2][4], al[2][4];
            #pragma unroll
            for (int mt=0;mt<2;mt++){
                u32 ad = stb + ((u32)((wm*32 + mt*16 + lrow)*20) + koff)*4;
                ldsm4(ah[mt], ad + U_AH*4);
                ldsm4(al[mt], ad + U_AL*4);
            }
            // B fragments: one x4 covers 16 n x 16 k = 2 nt groups.
            // r0=(n0-7,k0-7), r1=(n8-15,k0-7), r2=(n0-7,k8-15), r3=(n8-15,k8-15)
            // => nt=2p gets {r0, r2}, nt=2p+1 gets {r1, r3}.  (r4-bugfix)
            u32 bh[6][2], bl[6][2];
            #pragma unroll
            for (int p=0;p<3;p++){
                u32 bd = stb + ((u32)((wn*48 + p*16 + lrow)*20) + koff)*4;
                u32 r[4];
                ldsm4(r, bd + U_BH*4);
                bh[2*p][0]=r[0]; bh[2*p][1]=r[2]; bh[2*p+1][0]=r[1]; bh[2*p+1][1]=r[3];
                ldsm4(r, bd + U_BL*4);
                bl[2*p][0]=r[0]; bl[2*p][1]=r[2]; bl[2*p+1][0]=r[1]; bl[2*p+1][1]=r[3];
            }
            #pragma unroll
            for (int mt=0;mt<2;mt++)
                #pragma unroll
                for (int nt=0;nt<6;nt++){
                    mma16816(acc[mt][nt], ah[mt], bh[nt]);
                    mma16816(acc[mt][nt], ah[mt], bl[nt]);
                    mma16816(acc[mt][nt], al[mt], bh[nt]);
                }
        }

        if (it + 1 < NITS) cp_wait0();
        __syncthreads();
    }

    // store accumulators to this split's plane, layout [k][b][t][n]
    float* plane = g_part + (size_t)split * CN;
    #pragma unroll
    for (int mt=0;mt<2;mt++){
        #pragma unroll
        for (int nt=0;nt<6;nt++){
            int cbase = wn*48 + nt*8 + tig*2;
            #pragma unroll
            for (int h=0;h<2;h++){
                int r = r0 + wm*32 + mt*16 + g + h*8;
                int k = r >> 12, n = r & (NN-1);
                #pragma unroll
                for (int cc=0;cc<2;cc++){
                    int col = cbase + cc;
                    int b = col / TT, t = col - b*TT;
                    plane[(((size_t)(k*BB + b)*TT + t) << 12) + n] = acc[mt][nt][h*2+cc];
                }
            }
        }
    }
}

// ---------------------------------------------------------------- epilogue
__global__ __launch_bounds__(256) void epilogue_kernel(
    const float* __restrict__ x,
    const float* __restrict__ cheb_w,
    const float* __restrict__ gcn_w,
    const float* __restrict__ gcn_b,
    const float* __restrict__ glu1_w,
    const float* __restrict__ glu1_b,
    const float* __restrict__ glu2_w,
    const float* __restrict__ glu2_b,
    float* __restrict__ out)
{
    __shared__ __align__(16) float gws[TT*HIDD*FOUT];  // [t][j][o]
    __shared__ float cws[HIDD*3];
    __shared__ float w1s[FOUT*6*3], w2s[FOUT*6*3];
    __shared__ float gbs[FOUT], b1s[FOUT], b2s[FOUT];

    const int tid = threadIdx.x;
    for (int i=tid; i<TT*HIDD*FOUT; i+=256){
        int o = i % FOUT; int tj = i / FOUT; int t = tj >> 6; int j = tj & 63;
        gws[i] = gcn_w[(o*TT + t)*HIDD + j];
    }
    for (int i=tid; i<HIDD*3; i+=256) cws[i] = cheb_w[i];
    for (int i=tid; i<FOUT*18; i+=256){
        int kh = i % 3; int oc = i / 3;
        w1s[i] = glu1_w[(oc*3 + kh)*3 + 1];   // only kw=1 contributes (W==1)
        w2s[i] = glu2_w[(oc*3 + kh)*3 + 1];
    }
    if (tid < FOUT){ gbs[tid]=gcn_b[tid]; b1s[tid]=glu1_b[tid]; b2s[tid]=glu2_b[tid]; }
    __syncthreads();

    const int bn = blockIdx.x*256 + tid;
    const int b  = bn >> 12;
    const int n  = bn & (NN-1);

    float y[TT][3];
    #pragma unroll
    for (int k=0;k<3;k++)
        #pragma unroll
        for (int t=0;t<TT;t++){
            size_t off = (((size_t)(k*BB + b)*TT + t) << 12) + n;
            float s = 0.f;
            #pragma unroll
            for (int p=0;p<SPLITK;p++) s += g_part[(size_t)p*CN + off];
            y[t][k] = s;
        }

    ull acc[6];
    #pragma unroll
    for (int j=0;j<6;j++) acc[j] = 0ull;

    #pragma unroll
    for (int t=0;t<TT;t++){
        #pragma unroll 8
        for (int j=0;j<HIDD;j++){
            float c = y[t][0]*cws[j*3] + y[t][1]*cws[j*3+1] + y[t][2]*cws[j*3+2];
            c = fmaxf(c, 0.f);
            ull cd = f2dup(c);
            const float* gp = &gws[(t*HIDD + j)*FOUT];
            ulonglong2 g0 = *reinterpret_cast<const ulonglong2*>(gp);
            ulonglong2 g1 = *reinterpret_cast<const ulonglong2*>(gp+4);
            ulonglong2 g2 = *reinterpret_cast<const ulonglong2*>(gp+8);
            ffma2(acc[0], cd, g0.x); ffma2(acc[1], cd, g0.y);
            ffma2(acc[2], cd, g1.x); ffma2(acc[3], cd, g1.y);
            ffma2(acc[4], cd, g2.x); ffma2(acc[5], cd, g2.y);
        }
    }

    float xu[6][3], xv[6][3];
    #pragma unroll
    for (int c=0;c<6;c++){
        #pragma unroll
        for (int kh=0;kh<3;kh++){
            int pos = n + 2*kh - 2;
            bool ok = (pos >= 0) && (pos < NN);
            xu[c][kh] = ok ? x[((size_t)b*TT + c    )*NN + pos] : 0.f;
            xv[c][kh] = ok ? x[((size_t)b*TT + 6 + c)*NN + pos] : 0.f;
        }
    }

    #pragma unroll
    for (int o=0;o<FOUT;o++){
        float av = b1s[o], gv = b2s[o];
        #pragma unroll
        for (int c=0;c<6;c++)
            #pragma unroll
            for (int kh=0;kh<3;kh++){
                av += w1s[(o*6+c)*3+kh]*xu[c][kh];
                gv += w2s[(o*6+c)*3+kh]*xv[c][kh];
            }
        float sg = 1.f/(1.f + __expf(-gv));
        union { ull u; float f[2]; } vv; vv.u = acc[o>>1];
        float sgc = vv.f[o&1] + gbs[o];
        out[((size_t)b*FOUT + o)*NN + n] = av*sg + sgc;
    }
}

// ----------------------------------------------------------------
extern "C" void kernel_launch(void* const* d_in, const int* in_sizes, int n_in,
                              void* d_out, int out_size)
{
    (void)in_sizes; (void)n_in; (void)out_size;
    const float* x      = (const float*)d_in[0];
    const float* adj    = (const float*)d_in[1];
    const float* cheb_w = (const float*)d_in[2];
    const float* gcn_w  = (const float*)d_in[3];
    const float* gcn_b  = (const float*)d_in[4];
    const float* glu1_w = (const float*)d_in[5];
    const float* glu1_b = (const float*)d_in[6];
    const float* glu2_w = (const float*)d_in[7];
    const float* glu2_b = (const float*)d_in[8];
    float* out = (float*)d_out;

    split_x<<<(BT*NN/2)/256, 256>>>(x);

    cudaFuncSetAttribute(gemm_mma,
                         cudaFuncAttributeMaxDynamicSharedMemorySize, SMEM_TOTAL);
    gemm_mma<<<dim3(RTILES, SPLITK), 256, SMEM_TOTAL>>>(adj);

    epilogue_kernel<<<(BB*NN)/256, 256>>>(x, cheb_w, gcn_w, gcn_b,
                                          glu1_w, glu1_b, glu2_w, glu2_b, out);
}